// round 6
// baseline (speedup 1.0000x reference)
#include <cuda_runtime.h>
#include <math.h>

// Problem constants
#define MAX_NODES 50000
#define C_IN 256
#define C_OUT 10

// Scratch (static __device__ — no allocation allowed)
__device__ float g_sum[(size_t)MAX_NODES * C_IN];   // scatter-sum for layer-1 agg (then scaled to mean)
__device__ float g_h[(size_t)MAX_NODES * C_IN];     // hidden activations after relu
__device__ float g_cnt[MAX_NODES];                  // in-degree (float)
__device__ float g_p[MAX_NODES * C_OUT];            // h @ W2l  (pre-aggregation, linearity trick)
__device__ float g_q[MAX_NODES * C_OUT];            // h @ W2r + b2
__device__ float g_agg2[MAX_NODES * C_OUT];         // scatter-sum of g_p

// ---------------------------------------------------------------------------
// Vector reductions (sm_90+)
// ---------------------------------------------------------------------------
__device__ __forceinline__ void red_add_v4(float* addr, float4 v) {
    asm volatile("red.global.add.v4.f32 [%0], {%1, %2, %3, %4};"
                 :: "l"(addr), "f"(v.x), "f"(v.y), "f"(v.z), "f"(v.w) : "memory");
}
__device__ __forceinline__ void red_add_v2(float* addr, float2 v) {
    asm volatile("red.global.add.v2.f32 [%0], {%1, %2};"
                 :: "l"(addr), "f"(v.x), "f"(v.y) : "memory");
}

// ---------------------------------------------------------------------------
// Degree count: one thread per edge  (edge_index is int32: [2, E] row-major)
// ---------------------------------------------------------------------------
__global__ void count_k(const int* __restrict__ ei, int E, int M) {
    int e = blockIdx.x * blockDim.x + threadIdx.x;
    if (e >= E) return;
    int dst = __ldg(ei + E + e);
    if ((unsigned)dst < (unsigned)M) atomicAdd(&g_cnt[dst], 1.0f);
}

// ---------------------------------------------------------------------------
// Layer-1 scatter-add: warp per edge, 256 floats = 2 x float4 per lane
// ---------------------------------------------------------------------------
__global__ __launch_bounds__(256) void agg1_k(const float* __restrict__ x,
                                              const int* __restrict__ ei, int E, int M) {
    int w = (int)(((size_t)blockIdx.x * blockDim.x + threadIdx.x) >> 5);
    if (w >= E) return;
    int lane = threadIdx.x & 31;
    int src = __ldg(ei + w);
    int dst = __ldg(ei + E + w);
    if ((unsigned)src >= (unsigned)M || (unsigned)dst >= (unsigned)M) return;
    const float4* xr = (const float4*)(x + (size_t)src * C_IN);
    float* sr = g_sum + (size_t)dst * C_IN;
    float4 a0 = __ldg(xr + lane);
    float4 a1 = __ldg(xr + lane + 32);
    red_add_v4(sr + 4 * lane, a0);
    red_add_v4(sr + 4 * (lane + 32), a1);
}

// ---------------------------------------------------------------------------
// Scale sums to means: sum[row,:] *= 1/max(cnt,1)
// ---------------------------------------------------------------------------
__global__ void scale_k(int M) {
    int i = blockIdx.x * blockDim.x + threadIdx.x;  // float4 index
    if (i >= M * (C_IN / 4)) return;
    int node = i >> 6;
    float r = 1.0f / fmaxf(g_cnt[node], 1.0f);
    float4* p = (float4*)g_sum + i;
    float4 v = *p;
    v.x *= r; v.y *= r; v.z *= r; v.w *= r;
    *p = v;
}

// ---------------------------------------------------------------------------
// GEMM1: h = agg @ W1l + x @ W1r + b1, relu.  Treated as K=512 with two
// source pointers. Block tile 64x64, BK=16, 256 threads, 4x4 micro-tile.
// ---------------------------------------------------------------------------
__global__ __launch_bounds__(256) void gemm1_k(const float* __restrict__ x,
                                               const float* __restrict__ Wl,
                                               const float* __restrict__ Wr,
                                               const float* __restrict__ b1, int M) {
    __shared__ float As[16][68];   // [k][m], padded row keeps 16B alignment (68*4=272)
    __shared__ float Bs[16][64];   // [k][n]
    int tid = threadIdx.x;
    int row0 = blockIdx.y << 6;
    int col0 = blockIdx.x << 6;
    int am = tid >> 2;             // 0..63 (A row within tile)
    int ak = (tid & 3) << 2;       // 0,4,8,12 (A k within tile)
    int br = tid >> 4;             // 0..15 (B k within tile)
    int bc = (tid & 15) << 2;      // B col within tile
    int ty = tid >> 4, tx = tid & 15;
    bool arow_ok = (row0 + am) < M;
    float acc[4][4] = {};

    for (int kt = 0; kt < 512; kt += 16) {
        const float* A = (kt < 256) ? g_sum : x;
        const float* W = (kt < 256) ? Wl : Wr;
        int kk = kt & 255;
        float4 av = make_float4(0.f, 0.f, 0.f, 0.f);
        if (arow_ok) av = *(const float4*)(A + (size_t)(row0 + am) * 256 + kk + ak);
        As[ak + 0][am] = av.x; As[ak + 1][am] = av.y;
        As[ak + 2][am] = av.z; As[ak + 3][am] = av.w;
        float4 bv = *(const float4*)(W + (size_t)(kk + br) * 256 + col0 + bc);
        *(float4*)&Bs[br][bc] = bv;
        __syncthreads();
#pragma unroll
        for (int k = 0; k < 16; k++) {
            float4 a = *(const float4*)&As[k][ty << 2];
            float4 b = *(const float4*)&Bs[k][tx << 2];
            float ar[4] = {a.x, a.y, a.z, a.w};
            float bb[4] = {b.x, b.y, b.z, b.w};
#pragma unroll
            for (int i = 0; i < 4; i++)
#pragma unroll
                for (int j = 0; j < 4; j++) acc[i][j] += ar[i] * bb[j];
        }
        __syncthreads();
    }
    // Epilogue: + bias, relu, vectorized store
    float4 bias = *(const float4*)(b1 + col0 + (tx << 2));
#pragma unroll
    for (int i = 0; i < 4; i++) {
        int row = row0 + (ty << 2) + i;
        if (row < M) {
            float4 v;
            v.x = fmaxf(acc[i][0] + bias.x, 0.f);
            v.y = fmaxf(acc[i][1] + bias.y, 0.f);
            v.z = fmaxf(acc[i][2] + bias.z, 0.f);
            v.w = fmaxf(acc[i][3] + bias.w, 0.f);
            *(float4*)(g_h + (size_t)row * 256 + col0 + (tx << 2)) = v;
        }
    }
}

// ---------------------------------------------------------------------------
// Small GEMMs for layer 2: p = h@W2l, q = h@W2r + b2.  Warp per node,
// W matrices cached in smem, warp-shuffle reduction.
// ---------------------------------------------------------------------------
__global__ __launch_bounds__(256) void gemm2_k(const float* __restrict__ W2l,
                                               const float* __restrict__ W2r,
                                               const float* __restrict__ b2, int M) {
    __shared__ float sWl[C_IN * C_OUT];
    __shared__ float sWr[C_IN * C_OUT];
    for (int i = threadIdx.x; i < C_IN * C_OUT; i += 256) {
        sWl[i] = W2l[i];
        sWr[i] = W2r[i];
    }
    __syncthreads();
    int node = (int)(((size_t)blockIdx.x * blockDim.x + threadIdx.x) >> 5);
    if (node >= M) return;
    int lane = threadIdx.x & 31;
    const float* hr = g_h + (size_t)node * C_IN;
    float hv[8];
#pragma unroll
    for (int j = 0; j < 8; j++) hv[j] = hr[lane + 32 * j];
#pragma unroll
    for (int n = 0; n < C_OUT; n++) {
        float sl = 0.f, sr = 0.f;
#pragma unroll
        for (int j = 0; j < 8; j++) {
            int k = lane + 32 * j;
            sl += hv[j] * sWl[k * C_OUT + n];
            sr += hv[j] * sWr[k * C_OUT + n];
        }
#pragma unroll
        for (int o = 16; o > 0; o >>= 1) {
            sl += __shfl_xor_sync(0xFFFFFFFFu, sl, o);
            sr += __shfl_xor_sync(0xFFFFFFFFu, sr, o);
        }
        if (lane == 0) {
            g_p[node * C_OUT + n] = sl;
            g_q[node * C_OUT + n] = sr + b2[n];
        }
    }
}

// ---------------------------------------------------------------------------
// Layer-2 scatter-add over 10-dim features (linearity: agg(h)@W2l == agg(h@W2l))
// ---------------------------------------------------------------------------
__global__ void scatter2_k(const int* __restrict__ ei, int E, int M) {
    int e = blockIdx.x * blockDim.x + threadIdx.x;
    if (e >= E) return;
    int src = __ldg(ei + e);
    int dst = __ldg(ei + E + e);
    if ((unsigned)src >= (unsigned)M || (unsigned)dst >= (unsigned)M) return;
    const float2* ps = (const float2*)(g_p + src * C_OUT);  // 40B rows -> 8B aligned
    float* ds = g_agg2 + dst * C_OUT;
#pragma unroll
    for (int i = 0; i < 5; i++) {
        float2 v = __ldg(ps + i);
        red_add_v2(ds + 2 * i, v);
    }
}

// ---------------------------------------------------------------------------
// Final: out = log_softmax(agg2/cnt + q)
// ---------------------------------------------------------------------------
__global__ void final_k(float* __restrict__ out, int M) {
    int n = blockIdx.x * blockDim.x + threadIdx.x;
    if (n >= M) return;
    float r = 1.0f / fmaxf(g_cnt[n], 1.0f);
    float v[C_OUT];
    float m = -1e30f;
#pragma unroll
    for (int i = 0; i < C_OUT; i++) {
        v[i] = g_agg2[n * C_OUT + i] * r + g_q[n * C_OUT + i];
        m = fmaxf(m, v[i]);
    }
    float s = 0.f;
#pragma unroll
    for (int i = 0; i < C_OUT; i++) s += expf(v[i] - m);
    float lse = logf(s) + m;
#pragma unroll
    for (int i = 0; i < C_OUT; i++) out[n * C_OUT + i] = v[i] - lse;
}

// ---------------------------------------------------------------------------
// Launch
// ---------------------------------------------------------------------------
extern "C" void kernel_launch(void* const* d_in, const int* in_sizes, int n_in,
                              void* d_out, int out_size) {
    const float* x   = (const float*)d_in[0];
    const int* ei    = (const int*)d_in[1];   // int32! (JAX x64 disabled)
    const float* W1l = (const float*)d_in[2];
    const float* W1r = (const float*)d_in[3];
    const float* b1  = (const float*)d_in[4];
    const float* W2l = (const float*)d_in[5];
    const float* W2r = (const float*)d_in[6];
    const float* b2  = (const float*)d_in[7];
    float* out       = (float*)d_out;

    int M = in_sizes[0] / C_IN;   // 50000
    int E = in_sizes[1] / 2;      // 1600000

    void *p_sum, *p_cnt, *p_agg2;
    cudaGetSymbolAddress(&p_sum, g_sum);
    cudaGetSymbolAddress(&p_cnt, g_cnt);
    cudaGetSymbolAddress(&p_agg2, g_agg2);
    cudaMemsetAsync(p_sum, 0, (size_t)M * C_IN * sizeof(float));
    cudaMemsetAsync(p_cnt, 0, (size_t)M * sizeof(float));
    cudaMemsetAsync(p_agg2, 0, (size_t)M * C_OUT * sizeof(float));

    count_k<<<(E + 255) / 256, 256>>>(ei, E, M);
    agg1_k<<<(E + 7) / 8, 256>>>(x, ei, E, M);              // warp per edge
    scale_k<<<(M * (C_IN / 4) + 255) / 256, 256>>>(M);
    dim3 g1(4, (M + 63) / 64);
    gemm1_k<<<g1, 256>>>(x, W1l, W1r, b1, M);
    gemm2_k<<<(M + 7) / 8, 256>>>(W2l, W2r, b2, M);         // warp per node
    scatter2_k<<<(E + 255) / 256, 256>>>(ei, E, M);
    final_k<<<(M + 255) / 256, 256>>>(out, M);
}

// round 7
// speedup vs baseline: 1.2499x; 1.2499x over previous
#include <cuda_runtime.h>
#include <math.h>

#define MAX_NODES 50000
#define MAX_EDGES 1600000
#define C_IN 256
#define C_OUT 10

// Scratch (static __device__ — no allocation allowed)
__device__ float g_agg1[(size_t)MAX_NODES * C_IN];  // mean-aggregated x
__device__ float g_h[(size_t)MAX_NODES * C_IN];     // hidden activations after relu
__device__ int   g_deg[MAX_NODES];                  // in-degree
__device__ int   g_rowptr[MAX_NODES + 1];           // CSR row pointers (by dst)
__device__ int   g_cursor[MAX_NODES];               // fill cursors
__device__ int   g_srcs[MAX_EDGES];                 // CSR column (src) indices
__device__ float g_p[MAX_NODES * C_OUT];            // h @ W2l  (linearity trick)
__device__ float g_q[MAX_NODES * C_OUT];            // h @ W2r + b2
__device__ float g_agg2[MAX_NODES * C_OUT];         // scatter-sum of g_p

__device__ __forceinline__ void red_add_v2(float* addr, float2 v) {
    asm volatile("red.global.add.v2.f32 [%0], {%1, %2};"
                 :: "l"(addr), "f"(v.x), "f"(v.y) : "memory");
}

// ---------------------------------------------------------------------------
// Degree count (edge_index is int32: [2, E] row-major)
// ---------------------------------------------------------------------------
__global__ void count_k(const int* __restrict__ ei, int E, int M) {
    int e = blockIdx.x * blockDim.x + threadIdx.x;
    if (e >= E) return;
    int dst = __ldg(ei + E + e);
    if ((unsigned)dst < (unsigned)M) atomicAdd(&g_deg[dst], 1);
}

// ---------------------------------------------------------------------------
// Exclusive prefix sum of g_deg -> g_rowptr / g_cursor.  One block, 1024 thr,
// warp shuffle scan (2 syncs per 1024-chunk).
// ---------------------------------------------------------------------------
__global__ __launch_bounds__(1024) void scan_k(int M) {
    __shared__ int wsum[32];
    __shared__ int s_carry;
    int tid = threadIdx.x, lane = tid & 31, wid = tid >> 5;
    if (tid == 0) s_carry = 0;
    __syncthreads();
    for (int base = 0; base < M; base += 1024) {
        int i = base + tid;
        int v = (i < M) ? g_deg[i] : 0;
        int incl = v;
#pragma unroll
        for (int o = 1; o < 32; o <<= 1) {
            int t = __shfl_up_sync(0xFFFFFFFFu, incl, o);
            if (lane >= o) incl += t;
        }
        if (lane == 31) wsum[wid] = incl;
        __syncthreads();
        if (wid == 0) {
            int w = wsum[lane];
            int wi = w;
#pragma unroll
            for (int o = 1; o < 32; o <<= 1) {
                int t = __shfl_up_sync(0xFFFFFFFFu, wi, o);
                if (lane >= o) wi += t;
            }
            wsum[lane] = wi - w;   // exclusive warp offsets
        }
        __syncthreads();
        int excl = (incl - v) + wsum[wid] + s_carry;
        if (i < M) { g_rowptr[i] = excl; g_cursor[i] = excl; }
        __syncthreads();
        if (tid == 1023) s_carry = excl + v;  // chunk-inclusive total
        __syncthreads();
    }
    if (threadIdx.x == 0) g_rowptr[M] = s_carry;
}

// ---------------------------------------------------------------------------
// CSR fill: bucket src ids by dst
// ---------------------------------------------------------------------------
__global__ void fill_k(const int* __restrict__ ei, int E, int M) {
    int e = blockIdx.x * blockDim.x + threadIdx.x;
    if (e >= E) return;
    int src = __ldg(ei + e);
    int dst = __ldg(ei + E + e);
    if ((unsigned)src >= (unsigned)M || (unsigned)dst >= (unsigned)M) return;
    int pos = atomicAdd(&g_cursor[dst], 1);
    g_srcs[pos] = src;
}

// ---------------------------------------------------------------------------
// Layer-1 mean aggregation: warp per dst node, register accumulation,
// single write of the mean.  No atomics, no memset, no separate scale pass.
// ---------------------------------------------------------------------------
__global__ __launch_bounds__(256) void agg1_csr_k(const float* __restrict__ x, int M) {
    int node = blockIdx.x * 8 + (threadIdx.x >> 5);
    if (node >= M) return;
    int lane = threadIdx.x & 31;
    int beg = __ldg(g_rowptr + node);
    int end = __ldg(g_rowptr + node + 1);
    float4 a0 = make_float4(0.f, 0.f, 0.f, 0.f);
    float4 a1 = a0;
    int e = beg;
    for (; e + 4 <= end; e += 4) {
        int s0 = __ldg(g_srcs + e);
        int s1 = __ldg(g_srcs + e + 1);
        int s2 = __ldg(g_srcs + e + 2);
        int s3 = __ldg(g_srcs + e + 3);
        const float4* p0 = (const float4*)(x + (size_t)s0 * C_IN);
        const float4* p1 = (const float4*)(x + (size_t)s1 * C_IN);
        const float4* p2 = (const float4*)(x + (size_t)s2 * C_IN);
        const float4* p3 = (const float4*)(x + (size_t)s3 * C_IN);
        float4 v00 = __ldg(p0 + lane),      v01 = __ldg(p0 + lane + 32);
        float4 v10 = __ldg(p1 + lane),      v11 = __ldg(p1 + lane + 32);
        float4 v20 = __ldg(p2 + lane),      v21 = __ldg(p2 + lane + 32);
        float4 v30 = __ldg(p3 + lane),      v31 = __ldg(p3 + lane + 32);
        a0.x += v00.x + v10.x + v20.x + v30.x;
        a0.y += v00.y + v10.y + v20.y + v30.y;
        a0.z += v00.z + v10.z + v20.z + v30.z;
        a0.w += v00.w + v10.w + v20.w + v30.w;
        a1.x += v01.x + v11.x + v21.x + v31.x;
        a1.y += v01.y + v11.y + v21.y + v31.y;
        a1.z += v01.z + v11.z + v21.z + v31.z;
        a1.w += v01.w + v11.w + v21.w + v31.w;
    }
    for (; e < end; e++) {
        int s = __ldg(g_srcs + e);
        const float4* p = (const float4*)(x + (size_t)s * C_IN);
        float4 v0 = __ldg(p + lane), v1 = __ldg(p + lane + 32);
        a0.x += v0.x; a0.y += v0.y; a0.z += v0.z; a0.w += v0.w;
        a1.x += v1.x; a1.y += v1.y; a1.z += v1.z; a1.w += v1.w;
    }
    float r = 1.0f / fmaxf((float)(end - beg), 1.0f);
    a0.x *= r; a0.y *= r; a0.z *= r; a0.w *= r;
    a1.x *= r; a1.y *= r; a1.z *= r; a1.w *= r;
    float4* outp = (float4*)(g_agg1 + (size_t)node * C_IN);
    outp[lane] = a0;
    outp[lane + 32] = a1;
}

// ---------------------------------------------------------------------------
// GEMM1: h = relu(agg @ W1l + x @ W1r + b1).  K=512 (two sources).
// 128x128 block tile, BK=8, 256 threads, 8x8 microtile (split 4+4 @ +64).
// ---------------------------------------------------------------------------
__global__ __launch_bounds__(256) void gemm1_k(const float* __restrict__ x,
                                               const float* __restrict__ Wl,
                                               const float* __restrict__ Wr,
                                               const float* __restrict__ b1, int M) {
    __shared__ float As[8][132];   // [k][m] transposed, padded
    __shared__ float Bs[8][128];   // [k][n]
    int tid = threadIdx.x;
    int row0 = blockIdx.y << 7;
    int col0 = blockIdx.x << 7;
    int arow = tid >> 1;             // 0..127
    int ak   = (tid & 1) << 2;       // 0 or 4
    int bk   = tid >> 5;             // 0..7
    int bc   = (tid & 31) << 2;      // 0..124
    int tx = tid & 15, ty = tid >> 4;
    bool arow_ok = (row0 + arow) < M;
    float acc[8][8] = {};

    for (int kt = 0; kt < 512; kt += 8) {
        const float* A = (kt < 256) ? g_agg1 : x;
        const float* W = (kt < 256) ? Wl : Wr;
        int kk = kt & 255;
        float4 av = make_float4(0.f, 0.f, 0.f, 0.f);
        if (arow_ok) av = *(const float4*)(A + (size_t)(row0 + arow) * 256 + kk + ak);
        float4 bv = *(const float4*)(W + (size_t)(kk + bk) * 256 + col0 + bc);
        __syncthreads();
        As[ak + 0][arow] = av.x; As[ak + 1][arow] = av.y;
        As[ak + 2][arow] = av.z; As[ak + 3][arow] = av.w;
        *(float4*)&Bs[bk][bc] = bv;
        __syncthreads();
#pragma unroll
        for (int k = 0; k < 8; k++) {
            float4 a0 = *(const float4*)&As[k][ty << 2];
            float4 a1 = *(const float4*)&As[k][64 + (ty << 2)];
            float4 b0 = *(const float4*)&Bs[k][tx << 2];
            float4 b1v = *(const float4*)&Bs[k][64 + (tx << 2)];
            float ar[8] = {a0.x, a0.y, a0.z, a0.w, a1.x, a1.y, a1.z, a1.w};
            float br[8] = {b0.x, b0.y, b0.z, b0.w, b1v.x, b1v.y, b1v.z, b1v.w};
#pragma unroll
            for (int i = 0; i < 8; i++)
#pragma unroll
                for (int j = 0; j < 8; j++) acc[i][j] += ar[i] * br[j];
        }
    }
    // Epilogue: + bias, relu, vectorized store
    float4 bias0 = *(const float4*)(b1 + col0 + (tx << 2));
    float4 bias1 = *(const float4*)(b1 + col0 + 64 + (tx << 2));
#pragma unroll
    for (int i = 0; i < 8; i++) {
        int row = row0 + (ty << 2) + (i & 3) + ((i >= 4) ? 64 : 0);
        if (row < M) {
            float4 v0, v1;
            v0.x = fmaxf(acc[i][0] + bias0.x, 0.f);
            v0.y = fmaxf(acc[i][1] + bias0.y, 0.f);
            v0.z = fmaxf(acc[i][2] + bias0.z, 0.f);
            v0.w = fmaxf(acc[i][3] + bias0.w, 0.f);
            v1.x = fmaxf(acc[i][4] + bias1.x, 0.f);
            v1.y = fmaxf(acc[i][5] + bias1.y, 0.f);
            v1.z = fmaxf(acc[i][6] + bias1.z, 0.f);
            v1.w = fmaxf(acc[i][7] + bias1.w, 0.f);
            *(float4*)(g_h + (size_t)row * 256 + col0 + (tx << 2)) = v0;
            *(float4*)(g_h + (size_t)row * 256 + col0 + 64 + (tx << 2)) = v1;
        }
    }
}

// ---------------------------------------------------------------------------
// Layer 2 small GEMMs: p = h@W2l, q = h@W2r + b2.  Warp per node.
// ---------------------------------------------------------------------------
__global__ __launch_bounds__(256) void gemm2_k(const float* __restrict__ W2l,
                                               const float* __restrict__ W2r,
                                               const float* __restrict__ b2, int M) {
    __shared__ float sWl[C_IN * C_OUT];
    __shared__ float sWr[C_IN * C_OUT];
    for (int i = threadIdx.x; i < C_IN * C_OUT; i += 256) {
        sWl[i] = W2l[i];
        sWr[i] = W2r[i];
    }
    __syncthreads();
    int node = (int)(((size_t)blockIdx.x * blockDim.x + threadIdx.x) >> 5);
    if (node >= M) return;
    int lane = threadIdx.x & 31;
    const float* hr = g_h + (size_t)node * C_IN;
    float hv[8];
#pragma unroll
    for (int j = 0; j < 8; j++) hv[j] = hr[lane + 32 * j];
#pragma unroll
    for (int n = 0; n < C_OUT; n++) {
        float sl = 0.f, sr = 0.f;
#pragma unroll
        for (int j = 0; j < 8; j++) {
            int k = lane + 32 * j;
            sl += hv[j] * sWl[k * C_OUT + n];
            sr += hv[j] * sWr[k * C_OUT + n];
        }
#pragma unroll
        for (int o = 16; o > 0; o >>= 1) {
            sl += __shfl_xor_sync(0xFFFFFFFFu, sl, o);
            sr += __shfl_xor_sync(0xFFFFFFFFu, sr, o);
        }
        if (lane == 0) {
            g_p[node * C_OUT + n] = sl;
            g_q[node * C_OUT + n] = sr + b2[n];
        }
    }
}

// ---------------------------------------------------------------------------
// Layer-2 scatter-add over 10-dim features (agg(h)@W2l == agg(h@W2l))
// ---------------------------------------------------------------------------
__global__ void scatter2_k(const int* __restrict__ ei, int E, int M) {
    int e = blockIdx.x * blockDim.x + threadIdx.x;
    if (e >= E) return;
    int src = __ldg(ei + e);
    int dst = __ldg(ei + E + e);
    if ((unsigned)src >= (unsigned)M || (unsigned)dst >= (unsigned)M) return;
    const float2* ps = (const float2*)(g_p + src * C_OUT);
    float* ds = g_agg2 + dst * C_OUT;
#pragma unroll
    for (int i = 0; i < 5; i++) {
        float2 v = __ldg(ps + i);
        red_add_v2(ds + 2 * i, v);
    }
}

// ---------------------------------------------------------------------------
// Final: out = log_softmax(agg2/deg + q)
// ---------------------------------------------------------------------------
__global__ void final_k(float* __restrict__ out, int M) {
    int n = blockIdx.x * blockDim.x + threadIdx.x;
    if (n >= M) return;
    float r = 1.0f / fmaxf((float)__ldg(g_deg + n), 1.0f);
    float v[C_OUT];
    float m = -1e30f;
#pragma unroll
    for (int i = 0; i < C_OUT; i++) {
        v[i] = g_agg2[n * C_OUT + i] * r + g_q[n * C_OUT + i];
        m = fmaxf(m, v[i]);
    }
    float s = 0.f;
#pragma unroll
    for (int i = 0; i < C_OUT; i++) s += expf(v[i] - m);
    float lse = logf(s) + m;
#pragma unroll
    for (int i = 0; i < C_OUT; i++) out[n * C_OUT + i] = v[i] - lse;
}

// ---------------------------------------------------------------------------
// Launch
// ---------------------------------------------------------------------------
extern "C" void kernel_launch(void* const* d_in, const int* in_sizes, int n_in,
                              void* d_out, int out_size) {
    const float* x   = (const float*)d_in[0];
    const int* ei    = (const int*)d_in[1];   // int32 (JAX x64 disabled)
    const float* W1l = (const float*)d_in[2];
    const float* W1r = (const float*)d_in[3];
    const float* b1  = (const float*)d_in[4];
    const float* W2l = (const float*)d_in[5];
    const float* W2r = (const float*)d_in[6];
    const float* b2  = (const float*)d_in[7];
    float* out       = (float*)d_out;

    int M = in_sizes[0] / C_IN;   // 50000
    int E = in_sizes[1] / 2;      // 1600000
    if (E > MAX_EDGES) E = MAX_EDGES;

    void *p_deg, *p_agg2;
    cudaGetSymbolAddress(&p_deg, g_deg);
    cudaGetSymbolAddress(&p_agg2, g_agg2);
    cudaMemsetAsync(p_deg, 0, (size_t)M * sizeof(int));
    cudaMemsetAsync(p_agg2, 0, (size_t)M * C_OUT * sizeof(float));

    count_k<<<(E + 255) / 256, 256>>>(ei, E, M);
    scan_k<<<1, 1024>>>(M);
    fill_k<<<(E + 255) / 256, 256>>>(ei, E, M);
    agg1_csr_k<<<(M + 7) / 8, 256>>>(x, M);
    dim3 g1(2, (M + 127) / 128);
    gemm1_k<<<g1, 256>>>(x, W1l, W1r, b1, M);
    gemm2_k<<<(M + 7) / 8, 256>>>(W2l, W2r, b2, M);
    scatter2_k<<<(E + 255) / 256, 256>>>(ei, E, M);
    final_k<<<(M + 255) / 256, 256>>>(out, M);
}

// round 14
// speedup vs baseline: 1.9345x; 1.5477x over previous
#include <cuda_runtime.h>
#include <math.h>
#include <stdint.h>

#define MAX_NODES 50000
#define MAX_EDGES 1600000
#define C_IN 256
#define C_OUT 10

typedef unsigned int u32;

// Scratch (static __device__ — no allocation allowed)
__device__ float g_agg1[(size_t)MAX_NODES * C_IN];  // mean-aggregated x
__device__ float g_h[(size_t)MAX_NODES * C_IN];     // hidden activations after relu
__device__ int   g_deg[MAX_NODES];                  // in-degree
__device__ int   g_rowptr[MAX_NODES + 1];           // CSR row pointers (by dst)
__device__ int   g_cursor[MAX_NODES];               // fill cursors
__device__ int   g_srcs[MAX_EDGES];                 // CSR column (src) indices
__device__ float g_p[MAX_NODES * C_OUT];            // h @ W2l  (linearity trick)
__device__ float g_q[MAX_NODES * C_OUT];            // h @ W2r + b2

__device__ __forceinline__ u32 to_tf32(float f) {
    u32 r;
    asm("cvt.rna.tf32.f32 %0, %1;" : "=r"(r) : "f"(f));
    return r;
}

// ---------------------------------------------------------------------------
// Degree count (edge_index is int32: [2, E] row-major)
// ---------------------------------------------------------------------------
__global__ void count_k(const int* __restrict__ ei, int E, int M) {
    int e = blockIdx.x * blockDim.x + threadIdx.x;
    if (e >= E) return;
    int dst = __ldg(ei + E + e);
    if ((unsigned)dst < (unsigned)M) atomicAdd(&g_deg[dst], 1);
}

// ---------------------------------------------------------------------------
// Exclusive prefix sum of g_deg -> g_rowptr / g_cursor.  One block, 1024 thr.
// ---------------------------------------------------------------------------
__global__ __launch_bounds__(1024) void scan_k(int M) {
    __shared__ int wsum[32];
    __shared__ int s_carry;
    int tid = threadIdx.x, lane = tid & 31, wid = tid >> 5;
    if (tid == 0) s_carry = 0;
    __syncthreads();
    for (int base = 0; base < M; base += 1024) {
        int i = base + tid;
        int v = (i < M) ? g_deg[i] : 0;
        int incl = v;
#pragma unroll
        for (int o = 1; o < 32; o <<= 1) {
            int t = __shfl_up_sync(0xFFFFFFFFu, incl, o);
            if (lane >= o) incl += t;
        }
        if (lane == 31) wsum[wid] = incl;
        __syncthreads();
        if (wid == 0) {
            int w = wsum[lane];
            int wi = w;
#pragma unroll
            for (int o = 1; o < 32; o <<= 1) {
                int t = __shfl_up_sync(0xFFFFFFFFu, wi, o);
                if (lane >= o) wi += t;
            }
            wsum[lane] = wi - w;
        }
        __syncthreads();
        int excl = (incl - v) + wsum[wid] + s_carry;
        if (i < M) { g_rowptr[i] = excl; g_cursor[i] = excl; }
        __syncthreads();
        if (tid == 1023) s_carry = excl + v;
        __syncthreads();
    }
    if (threadIdx.x == 0) g_rowptr[M] = s_carry;
}

// ---------------------------------------------------------------------------
// CSR fill: bucket src ids by dst
// ---------------------------------------------------------------------------
__global__ void fill_k(const int* __restrict__ ei, int E, int M) {
    int e = blockIdx.x * blockDim.x + threadIdx.x;
    if (e >= E) return;
    int src = __ldg(ei + e);
    int dst = __ldg(ei + E + e);
    if ((unsigned)dst >= (unsigned)M) return;
    int pos = atomicAdd(&g_cursor[dst], 1);
    g_srcs[pos] = src;
}

// ---------------------------------------------------------------------------
// Layer-1 mean aggregation: warp per dst node, register accumulation.
// ---------------------------------------------------------------------------
__global__ __launch_bounds__(256) void agg1_csr_k(const float* __restrict__ x, int M) {
    int node = blockIdx.x * 8 + (threadIdx.x >> 5);
    if (node >= M) return;
    int lane = threadIdx.x & 31;
    int beg = __ldg(g_rowptr + node);
    int end = __ldg(g_rowptr + node + 1);
    float4 a0 = make_float4(0.f, 0.f, 0.f, 0.f);
    float4 a1 = a0;
    int e = beg;
    for (; e + 4 <= end; e += 4) {
        int s0 = __ldg(g_srcs + e);
        int s1 = __ldg(g_srcs + e + 1);
        int s2 = __ldg(g_srcs + e + 2);
        int s3 = __ldg(g_srcs + e + 3);
        const float4* p0 = (const float4*)(x + (size_t)s0 * C_IN);
        const float4* p1 = (const float4*)(x + (size_t)s1 * C_IN);
        const float4* p2 = (const float4*)(x + (size_t)s2 * C_IN);
        const float4* p3 = (const float4*)(x + (size_t)s3 * C_IN);
        float4 v00 = __ldg(p0 + lane),      v01 = __ldg(p0 + lane + 32);
        float4 v10 = __ldg(p1 + lane),      v11 = __ldg(p1 + lane + 32);
        float4 v20 = __ldg(p2 + lane),      v21 = __ldg(p2 + lane + 32);
        float4 v30 = __ldg(p3 + lane),      v31 = __ldg(p3 + lane + 32);
        a0.x += v00.x + v10.x + v20.x + v30.x;
        a0.y += v00.y + v10.y + v20.y + v30.y;
        a0.z += v00.z + v10.z + v20.z + v30.z;
        a0.w += v00.w + v10.w + v20.w + v30.w;
        a1.x += v01.x + v11.x + v21.x + v31.x;
        a1.y += v01.y + v11.y + v21.y + v31.y;
        a1.z += v01.z + v11.z + v21.z + v31.z;
        a1.w += v01.w + v11.w + v21.w + v31.w;
    }
    for (; e < end; e++) {
        int s = __ldg(g_srcs + e);
        const float4* p = (const float4*)(x + (size_t)s * C_IN);
        float4 v0 = __ldg(p + lane), v1 = __ldg(p + lane + 32);
        a0.x += v0.x; a0.y += v0.y; a0.z += v0.z; a0.w += v0.w;
        a1.x += v1.x; a1.y += v1.y; a1.z += v1.z; a1.w += v1.w;
    }
    float r = 1.0f / fmaxf((float)(end - beg), 1.0f);
    a0.x *= r; a0.y *= r; a0.z *= r; a0.w *= r;
    a1.x *= r; a1.y *= r; a1.z *= r; a1.w *= r;
    float4* outp = (float4*)(g_agg1 + (size_t)node * C_IN);
    outp[lane] = a0;
    outp[lane + 32] = a1;
}

// ---------------------------------------------------------------------------
// GEMM1 (tensor cores, tf32): h = relu(agg @ W1l + x @ W1r + b1).
// K=512 (two sources). 128x128 block tile, BK=16, 8 warps x (32x64) warp
// tiles, mma.sync.m16n8k8.tf32.  Smem padded conflict-free:
//   As[m][k] row stride 20 -> banks (grp*20+tig)%32 all distinct
//   Bs[k][n] row stride 136 -> banks (tig*8+grp)%32 all distinct
// ---------------------------------------------------------------------------
__global__ __launch_bounds__(256) void gemm1_k(const float* __restrict__ x,
                                               const float* __restrict__ Wl,
                                               const float* __restrict__ Wr,
                                               const float* __restrict__ b1, int M) {
    __shared__ float As[128][20];
    __shared__ float Bs[16][136];
    int tid = threadIdx.x;
    int wid = tid >> 5, lane = tid & 31;
    int grp = lane >> 2, tig = lane & 3;
    int warp_m = (wid & 3) << 5;     // 0,32,64,96
    int warp_n = (wid >> 2) << 6;    // 0,64
    int row0 = blockIdx.y << 7;
    int col0 = blockIdx.x << 7;

    // global->smem load assignments
    int ar = tid >> 1;               // A row 0..127
    int ah = (tid & 1) << 3;         // A k offset 0 or 8
    int bkk = tid >> 4;              // B k row 0..15
    int bn = (tid & 15) << 3;        // B n offset 0..120
    bool arow_ok = (row0 + ar) < M;

    float c[2][8][4];
#pragma unroll
    for (int i = 0; i < 2; i++)
#pragma unroll
        for (int j = 0; j < 8; j++)
#pragma unroll
            for (int r = 0; r < 4; r++) c[i][j][r] = 0.f;

    for (int kt = 0; kt < 512; kt += 16) {
        const float* A = (kt < 256) ? g_agg1 : x;
        const float* W = (kt < 256) ? Wl : Wr;
        int kk = kt & 255;
        float4 av0 = make_float4(0.f,0.f,0.f,0.f), av1 = av0;
        if (arow_ok) {
            const float* ap = A + (size_t)(row0 + ar) * 256 + kk + ah;
            av0 = *(const float4*)ap;
            av1 = *(const float4*)(ap + 4);
        }
        const float* wp = W + (size_t)(kk + bkk) * 256 + col0 + bn;
        float4 bv0 = *(const float4*)wp;
        float4 bv1 = *(const float4*)(wp + 4);
        __syncthreads();
        As[ar][ah + 0] = __uint_as_float(to_tf32(av0.x));
        As[ar][ah + 1] = __uint_as_float(to_tf32(av0.y));
        As[ar][ah + 2] = __uint_as_float(to_tf32(av0.z));
        As[ar][ah + 3] = __uint_as_float(to_tf32(av0.w));
        As[ar][ah + 4] = __uint_as_float(to_tf32(av1.x));
        As[ar][ah + 5] = __uint_as_float(to_tf32(av1.y));
        As[ar][ah + 6] = __uint_as_float(to_tf32(av1.z));
        As[ar][ah + 7] = __uint_as_float(to_tf32(av1.w));
        Bs[bkk][bn + 0] = __uint_as_float(to_tf32(bv0.x));
        Bs[bkk][bn + 1] = __uint_as_float(to_tf32(bv0.y));
        Bs[bkk][bn + 2] = __uint_as_float(to_tf32(bv0.z));
        Bs[bkk][bn + 3] = __uint_as_float(to_tf32(bv0.w));
        Bs[bkk][bn + 4] = __uint_as_float(to_tf32(bv1.x));
        Bs[bkk][bn + 5] = __uint_as_float(to_tf32(bv1.y));
        Bs[bkk][bn + 6] = __uint_as_float(to_tf32(bv1.z));
        Bs[bkk][bn + 7] = __uint_as_float(to_tf32(bv1.w));
        __syncthreads();

#pragma unroll
        for (int s = 0; s < 2; s++) {
            int k8 = s << 3;
            u32 a[2][4], b[8][2];
#pragma unroll
            for (int mt = 0; mt < 2; mt++) {
                int m0 = warp_m + (mt << 4) + grp;
                a[mt][0] = __float_as_uint(As[m0    ][k8 + tig]);
                a[mt][1] = __float_as_uint(As[m0 + 8][k8 + tig]);
                a[mt][2] = __float_as_uint(As[m0    ][k8 + tig + 4]);
                a[mt][3] = __float_as_uint(As[m0 + 8][k8 + tig + 4]);
            }
#pragma unroll
            for (int nt = 0; nt < 8; nt++) {
                int n0 = warp_n + (nt << 3) + grp;
                b[nt][0] = __float_as_uint(Bs[k8 + tig    ][n0]);
                b[nt][1] = __float_as_uint(Bs[k8 + tig + 4][n0]);
            }
#pragma unroll
            for (int mt = 0; mt < 2; mt++)
#pragma unroll
                for (int nt = 0; nt < 8; nt++) {
                    asm volatile(
                        "mma.sync.aligned.m16n8k8.row.col.f32.tf32.tf32.f32 "
                        "{%0,%1,%2,%3}, {%4,%5,%6,%7}, {%8,%9}, {%0,%1,%2,%3};"
                        : "+f"(c[mt][nt][0]), "+f"(c[mt][nt][1]),
                          "+f"(c[mt][nt][2]), "+f"(c[mt][nt][3])
                        : "r"(a[mt][0]), "r"(a[mt][1]), "r"(a[mt][2]), "r"(a[mt][3]),
                          "r"(b[nt][0]), "r"(b[nt][1]));
                }
        }
    }

    // Epilogue: bias + relu, float2 stores
#pragma unroll
    for (int nt = 0; nt < 8; nt++) {
        int col = col0 + warp_n + (nt << 3) + (tig << 1);
        float bx = __ldg(b1 + col);
        float by = __ldg(b1 + col + 1);
#pragma unroll
        for (int mt = 0; mt < 2; mt++) {
            int r0 = row0 + warp_m + (mt << 4) + grp;
            if (r0 < M) {
                float2 v;
                v.x = fmaxf(c[mt][nt][0] + bx, 0.f);
                v.y = fmaxf(c[mt][nt][1] + by, 0.f);
                *(float2*)(g_h + (size_t)r0 * 256 + col) = v;
            }
            if (r0 + 8 < M) {
                float2 v;
                v.x = fmaxf(c[mt][nt][2] + bx, 0.f);
                v.y = fmaxf(c[mt][nt][3] + by, 0.f);
                *(float2*)(g_h + (size_t)(r0 + 8) * 256 + col) = v;
            }
        }
    }
}

// ---------------------------------------------------------------------------
// Layer 2 small GEMMs: p = h@W2l, q = h@W2r + b2.  Warp per node.
// ---------------------------------------------------------------------------
__global__ __launch_bounds__(256) void gemm2_k(const float* __restrict__ W2l,
                                               const float* __restrict__ W2r,
                                               const float* __restrict__ b2, int M) {
    __shared__ float sWl[C_IN * C_OUT];
    __shared__ float sWr[C_IN * C_OUT];
    for (int i = threadIdx.x; i < C_IN * C_OUT; i += 256) {
        sWl[i] = W2l[i];
        sWr[i] = W2r[i];
    }
    __syncthreads();
    int node = (int)(((size_t)blockIdx.x * blockDim.x + threadIdx.x) >> 5);
    if (node >= M) return;
    int lane = threadIdx.x & 31;
    const float* hr = g_h + (size_t)node * C_IN;
    float hv[8];
#pragma unroll
    for (int j = 0; j < 8; j++) hv[j] = hr[lane + 32 * j];
#pragma unroll
    for (int n = 0; n < C_OUT; n++) {
        float sl = 0.f, sr = 0.f;
#pragma unroll
        for (int j = 0; j < 8; j++) {
            int k = lane + 32 * j;
            sl += hv[j] * sWl[k * C_OUT + n];
            sr += hv[j] * sWr[k * C_OUT + n];
        }
#pragma unroll
        for (int o = 16; o > 0; o >>= 1) {
            sl += __shfl_xor_sync(0xFFFFFFFFu, sl, o);
            sr += __shfl_xor_sync(0xFFFFFFFFu, sr, o);
        }
        if (lane == 0) {
            g_p[node * C_OUT + n] = sl;
            g_q[node * C_OUT + n] = sr + b2[n];
        }
    }
}

// ---------------------------------------------------------------------------
// Fused layer-2 aggregation + log_softmax: warp per node over CSR,
// 10 register accumulators, xor-reduce, lane 0 writes the output row.
// out = log_softmax(mean_agg(p) + q)
// ---------------------------------------------------------------------------
__global__ __launch_bounds__(256) void agg2_final_k(float* __restrict__ out, int M) {
    int node = blockIdx.x * 8 + (threadIdx.x >> 5);
    if (node >= M) return;
    int lane = threadIdx.x & 31;
    int beg = __ldg(g_rowptr + node);
    int end = __ldg(g_rowptr + node + 1);
    float acc[C_OUT];
#pragma unroll
    for (int i = 0; i < C_OUT; i++) acc[i] = 0.f;
    for (int e = beg + lane; e < end; e += 32) {
        int s = __ldg(g_srcs + e);
        const float2* ps = (const float2*)(g_p + s * C_OUT);
#pragma unroll
        for (int i = 0; i < 5; i++) {
            float2 v = __ldg(ps + i);
            acc[2 * i] += v.x;
            acc[2 * i + 1] += v.y;
        }
    }
#pragma unroll
    for (int i = 0; i < C_OUT; i++)
#pragma unroll
        for (int o = 16; o > 0; o >>= 1)
            acc[i] += __shfl_xor_sync(0xFFFFFFFFu, acc[i], o);
    if (lane == 0) {
        float r = 1.0f / fmaxf((float)(end - beg), 1.0f);
        const float* qp = g_q + node * C_OUT;
        float v[C_OUT];
        float m = -1e30f;
#pragma unroll
        for (int i = 0; i < C_OUT; i++) {
            v[i] = acc[i] * r + qp[i];
            m = fmaxf(m, v[i]);
        }
        float s = 0.f;
#pragma unroll
        for (int i = 0; i < C_OUT; i++) s += expf(v[i] - m);
        float lse = logf(s) + m;
        float2* op = (float2*)(out + node * C_OUT);
#pragma unroll
        for (int i = 0; i < 5; i++)
            op[i] = make_float2(v[2 * i] - lse, v[2 * i + 1] - lse);
    }
}

// ---------------------------------------------------------------------------
// Launch
// ---------------------------------------------------------------------------
extern "C" void kernel_launch(void* const* d_in, const int* in_sizes, int n_in,
                              void* d_out, int out_size) {
    const float* x   = (const float*)d_in[0];
    const int* ei    = (const int*)d_in[1];   // int32 (JAX x64 disabled)
    const float* W1l = (const float*)d_in[2];
    const float* W1r = (const float*)d_in[3];
    const float* b1  = (const float*)d_in[4];
    const float* W2l = (const float*)d_in[5];
    const float* W2r = (const float*)d_in[6];
    const float* b2  = (const float*)d_in[7];
    float* out       = (float*)d_out;

    int M = in_sizes[0] / C_IN;   // 50000
    int E = in_sizes[1] / 2;      // 1600000
    if (E > MAX_EDGES) E = MAX_EDGES;

    void* p_deg;
    cudaGetSymbolAddress(&p_deg, g_deg);
    cudaMemsetAsync(p_deg, 0, (size_t)M * sizeof(int));

    count_k<<<(E + 255) / 256, 256>>>(ei, E, M);
    scan_k<<<1, 1024>>>(M);
    fill_k<<<(E + 255) / 256, 256>>>(ei, E, M);
    agg1_csr_k<<<(M + 7) / 8, 256>>>(x, M);
    dim3 g1(2, (M + 127) / 128);
    gemm1_k<<<g1, 256>>>(x, W1l, W1r, b1, M);
    gemm2_k<<<(M + 7) / 8, 256>>>(W2l, W2r, b2, M);
    agg2_final_k<<<(M + 7) / 8, 256>>>(out, M);
}